// round 1
// baseline (speedup 1.0000x reference)
#include <cuda_runtime.h>
#include <cuda_bf16.h>

// LinearNavigator: preproc -> LSTMCell(2->20) -> LSTMCell(20->20) -> Linear(20->1) -> x[1..5]
// B = 1048576, H = 20.
// Outputs concatenated: out[B,5], h_stack[2,B,20], c_stack[2,B,20]  (all fp32)

#define NB 1048576
#define HDIM 20

__device__ __forceinline__ float sigmoid_(float x) {
    return __fdividef(1.0f, 1.0f + __expf(-x));
}
__device__ __forceinline__ float tanh_(float x) {
    // 1 - 2/(e^{2x}+1): inf-safe at both ends
    float e = __expf(2.0f * x);
    return 1.0f - __fdividef(2.0f, e + 1.0f);
}

__global__ __launch_bounds__(128)
void navi_kernel(const float* __restrict__ inp,
                 const float* __restrict__ hidden,
                 const float* __restrict__ cell,
                 const float* __restrict__ W_ih1, const float* __restrict__ W_hh1,
                 const float* __restrict__ b_ih1, const float* __restrict__ b_hh1,
                 const float* __restrict__ W_ih2, const float* __restrict__ W_hh2,
                 const float* __restrict__ b_ih2, const float* __restrict__ b_hh2,
                 const float* __restrict__ W_out, const float* __restrict__ b_out,
                 float* __restrict__ out)
{
    __shared__ float sWih1[80 * 2];
    __shared__ float sWhh1[80 * HDIM];
    __shared__ float sb1[80];
    __shared__ float sWih2[80 * HDIM];
    __shared__ float sWhh2[80 * HDIM];
    __shared__ float sb2[80];
    __shared__ float sWo[HDIM];
    __shared__ float sbo;

    const int t = threadIdx.x;
    for (int i = t; i < 160;  i += blockDim.x) sWih1[i] = W_ih1[i];
    for (int i = t; i < 1600; i += blockDim.x) sWhh1[i] = W_hh1[i];
    for (int i = t; i < 1600; i += blockDim.x) sWih2[i] = W_ih2[i];
    for (int i = t; i < 1600; i += blockDim.x) sWhh2[i] = W_hh2[i];
    for (int i = t; i < 80;   i += blockDim.x) sb1[i] = b_ih1[i] + b_hh1[i];
    for (int i = t; i < 80;   i += blockDim.x) sb2[i] = b_ih2[i] + b_hh2[i];
    for (int i = t; i < HDIM; i += blockDim.x) sWo[i] = W_out[i];
    if (t == 0) sbo = b_out[0];
    __syncthreads();

    const int b = blockIdx.x * blockDim.x + t;
    if (b >= NB) return;

    // ---------------- preproc ----------------
    const float v  = inp[b];
    const float av = fabsf(v);
    const float THR = 4.5399929762484854e-05f;  // exp(-10)
    const float E10 = 22026.465794806718f;      // exp(10)
    float x0, x1;
    if (av >= THR) {
        x0 = __logf(av + 1e-8f) * 0.1f;
        x1 = (v > 0.0f) ? 1.0f : -1.0f;
    } else {
        x0 = -1.0f;
        x1 = E10 * v;
    }

    // ---------------- load states (vectorized) ----------------
    float h0[HDIM], c0[HDIM];
    {
        const float4* hp = reinterpret_cast<const float4*>(hidden + (size_t)b * HDIM);
        const float4* cp = reinterpret_cast<const float4*>(cell   + (size_t)b * HDIM);
        #pragma unroll
        for (int q = 0; q < 5; q++) {
            float4 hv = hp[q];
            h0[4*q+0] = hv.x; h0[4*q+1] = hv.y; h0[4*q+2] = hv.z; h0[4*q+3] = hv.w;
            float4 cv = cp[q];
            c0[4*q+0] = cv.x; c0[4*q+1] = cv.y; c0[4*q+2] = cv.z; c0[4*q+3] = cv.w;
        }
    }

    // ---------------- LSTM layer 1 ----------------
    float hn1[HDIM];
    #pragma unroll 1
    for (int j = 0; j < HDIM; j++) {
        float gi = sb1[j]      + x0 * sWih1[2*j]           + x1 * sWih1[2*j + 1];
        float gf = sb1[j + 20] + x0 * sWih1[2*(j+20)]      + x1 * sWih1[2*(j+20) + 1];
        float gg = sb1[j + 40] + x0 * sWih1[2*(j+40)]      + x1 * sWih1[2*(j+40) + 1];
        float go = sb1[j + 60] + x0 * sWih1[2*(j+60)]      + x1 * sWih1[2*(j+60) + 1];
        const float* wr = &sWhh1[j * HDIM];
        #pragma unroll
        for (int k = 0; k < HDIM; k++) {
            const float hk = h0[k];
            gi += hk * wr[k];
            gf += hk * wr[20*HDIM + k];
            gg += hk * wr[40*HDIM + k];
            go += hk * wr[60*HDIM + k];
        }
        const float cn = sigmoid_(gf) * c0[j] + sigmoid_(gi) * tanh_(gg);
        hn1[j] = sigmoid_(go) * tanh_(cn);
        c0[j] = cn;  // reuse as c0_new staging
    }

    // ---------------- load layer-2 states ----------------
    float h1[HDIM], c1[HDIM];
    {
        const float4* hp = reinterpret_cast<const float4*>(hidden + (size_t)NB * HDIM + (size_t)b * HDIM);
        const float4* cp = reinterpret_cast<const float4*>(cell   + (size_t)NB * HDIM + (size_t)b * HDIM);
        #pragma unroll
        for (int q = 0; q < 5; q++) {
            float4 hv = hp[q];
            h1[4*q+0] = hv.x; h1[4*q+1] = hv.y; h1[4*q+2] = hv.z; h1[4*q+3] = hv.w;
            float4 cv = cp[q];
            c1[4*q+0] = cv.x; c1[4*q+1] = cv.y; c1[4*q+2] = cv.z; c1[4*q+3] = cv.w;
        }
    }

    // ---------------- LSTM layer 2 ----------------
    float hn2[HDIM];
    #pragma unroll 1
    for (int j = 0; j < HDIM; j++) {
        float gi = sb2[j];
        float gf = sb2[j + 20];
        float gg = sb2[j + 40];
        float go = sb2[j + 60];
        const float* wi = &sWih2[j * HDIM];
        const float* wr = &sWhh2[j * HDIM];
        #pragma unroll
        for (int k = 0; k < HDIM; k++) {
            const float xk = hn1[k];
            const float hk = h1[k];
            gi += xk * wi[k]           + hk * wr[k];
            gf += xk * wi[20*HDIM + k] + hk * wr[20*HDIM + k];
            gg += xk * wi[40*HDIM + k] + hk * wr[40*HDIM + k];
            go += xk * wi[60*HDIM + k] + hk * wr[60*HDIM + k];
        }
        const float cn = sigmoid_(gf) * c1[j] + sigmoid_(gi) * tanh_(gg);
        hn2[j] = sigmoid_(go) * tanh_(cn);
        c1[j] = cn;
    }

    // ---------------- output head ----------------
    float o = sbo;
    #pragma unroll
    for (int k = 0; k < HDIM; k++) o += hn2[k] * sWo[k];

    // ---------------- stores ----------------
    // out[B,5]
    float* out5 = out + (size_t)b * 5;
    #pragma unroll
    for (int s = 0; s < 5; s++) out5[s] = o * (float)(s + 1);

    // h_stack[2,B,H] then c_stack[2,B,H]
    float* hbase = out + (size_t)5 * NB;
    float* cbase = out + (size_t)5 * NB + (size_t)2 * NB * HDIM;
    float4* h0p = reinterpret_cast<float4*>(hbase + (size_t)b * HDIM);
    float4* h1p = reinterpret_cast<float4*>(hbase + (size_t)NB * HDIM + (size_t)b * HDIM);
    float4* c0p = reinterpret_cast<float4*>(cbase + (size_t)b * HDIM);
    float4* c1p = reinterpret_cast<float4*>(cbase + (size_t)NB * HDIM + (size_t)b * HDIM);
    #pragma unroll
    for (int q = 0; q < 5; q++) {
        h0p[q] = make_float4(hn1[4*q], hn1[4*q+1], hn1[4*q+2], hn1[4*q+3]);
        h1p[q] = make_float4(hn2[4*q], hn2[4*q+1], hn2[4*q+2], hn2[4*q+3]);
        c0p[q] = make_float4(c0[4*q],  c0[4*q+1],  c0[4*q+2],  c0[4*q+3]);
        c1p[q] = make_float4(c1[4*q],  c1[4*q+1],  c1[4*q+2],  c1[4*q+3]);
    }
}

extern "C" void kernel_launch(void* const* d_in, const int* in_sizes, int n_in,
                              void* d_out, int out_size) {
    const float* inp    = (const float*)d_in[0];
    const float* hidden = (const float*)d_in[1];
    const float* cell   = (const float*)d_in[2];
    const float* W_ih1  = (const float*)d_in[3];
    const float* W_hh1  = (const float*)d_in[4];
    const float* b_ih1  = (const float*)d_in[5];
    const float* b_hh1  = (const float*)d_in[6];
    const float* W_ih2  = (const float*)d_in[7];
    const float* W_hh2  = (const float*)d_in[8];
    const float* b_ih2  = (const float*)d_in[9];
    const float* b_hh2  = (const float*)d_in[10];
    const float* W_out  = (const float*)d_in[11];
    const float* b_out  = (const float*)d_in[12];
    float* out = (float*)d_out;

    const int threads = 128;
    const int blocks = NB / threads;
    navi_kernel<<<blocks, threads>>>(inp, hidden, cell,
                                     W_ih1, W_hh1, b_ih1, b_hh1,
                                     W_ih2, W_hh2, b_ih2, b_hh2,
                                     W_out, b_out, out);
}